// round 15
// baseline (speedup 1.0000x reference)
#include <cuda_runtime.h>
#include <cuda.h>
#include <cstdint>

typedef unsigned long long ull;
#define FULLMASK 0xffffffffu
#define BAR(id, n) asm volatile("bar.sync %0, %1;" :: "r"(id), "r"(n) : "memory")

__device__ __forceinline__ ull pk2(float x, float y) {
    ull r; asm("mov.b64 %0, {%1, %2};" : "=l"(r) : "f"(x), "f"(y)); return r;
}
__device__ __forceinline__ float2 upk2(ull p) {
    float2 t; asm("mov.b64 {%0, %1}, %2;" : "=f"(t.x), "=f"(t.y) : "l"(p)); return t;
}
__device__ __forceinline__ void fma2(ull& d, ull a, ull b) {
    asm("fma.rn.f32x2 %0, %1, %2, %0;" : "+l"(d) : "l"(a), "l"(b));
}
__device__ __forceinline__ void add2(ull& d, ull a) {
    asm("add.rn.f32x2 %0, %0, %1;" : "+l"(d) : "l"(a));
}
__device__ __forceinline__ float tf32r(float x) {
    uint32_t o; asm("cvt.rna.tf32.f32 %0, %1;" : "=r"(o) : "f"(x));
    return __uint_as_float(o);
}
__device__ __forceinline__ void mbar_wait(uint32_t mb, uint32_t ph) {
    uint32_t done;
    asm volatile("{\n\t.reg .pred p;\n\t"
        "mbarrier.try_wait.parity.acquire.cta.shared::cta.b64 p, [%1], %2;\n\t"
        "selp.b32 %0, 1, 0, p;\n\t}" : "=r"(done) : "r"(mb), "r"(ph) : "memory");
    while (!done) {
        asm volatile("{\n\t.reg .pred p;\n\t"
            "mbarrier.try_wait.parity.acquire.cta.shared::cta.b64 p, [%1], %2, 10000000;\n\t"
            "selp.b32 %0, 1, 0, p;\n\t}" : "=r"(done) : "r"(mb), "r"(ph) : "memory");
    }
}
__device__ __forceinline__ void mma8(float* c, uint32_t a0, uint32_t a1, uint32_t a2,
                                     uint32_t a3, uint32_t b0, uint32_t b1) {
    asm volatile("mma.sync.aligned.m16n8k8.row.col.f32.tf32.tf32.f32 "
                 "{%0,%1,%2,%3}, {%4,%5,%6,%7}, {%8,%9}, {%0,%1,%2,%3};"
                 : "+f"(c[0]), "+f"(c[1]), "+f"(c[2]), "+f"(c[3])
                 : "r"(a0), "r"(a1), "r"(a2), "r"(a3), "r"(b0), "r"(b1));
}

// ---- smem layout (bytes) ----
#define BUFB   32768                 // 256 rows x 32 floats (SW128)
#define W1POFF (4 * BUFB)            // 131072: W1 packed ull[256][6] = 12288
#define SCROFF (W1POFF + 12288)      // 143360: 4 slices * 256 rows * 5 ull = 40960
#define MBOFF  (SCROFF + 40960)      // 184320: full[4] @ +0, empty[4] @ +32
#define K2AOFF (MBOFF + 64)          // 184384: A [64][20] = 5120
#define K2BOFF (K2AOFF + 5120)       // 189504: B [16][136] = 8704
#define WT1OFF (K2BOFF + 8704)       // 198208: Wt1^T packed [5][512] ull = 20480
#define BT1OFF (WT1OFF + 20480)      // 218688: bt1 2048
#define B1OFF  (BT1OFF + 2048)       // 220736: b1 64
#define HSOFF  (B1OFF + 64)          // 220800: hs [8][10] = 320
#define SMEMT  (HSOFF + 320)         // 221120

__global__ void __launch_bounds__(384, 1)
fused_all(const __grid_constant__ CUtensorMap tmap,
          const float* __restrict__ W1, const float* __restrict__ b1,
          const float* __restrict__ Wt1, const float* __restrict__ bt1,
          const float* __restrict__ A, const float* __restrict__ Bw,
          const float* __restrict__ bt2, float* __restrict__ out, int B)
{
    extern __shared__ char sm[];
    const uint32_t smb = (uint32_t)__cvta_generic_to_shared(sm);
    const int t = threadIdx.x;
    const int G = gridDim.x, bid = blockIdx.x;

    if (t < 256) {
        // ================= k1 + fused from_neighs epilogue =================
        ull* w1p = (ull*)(sm + W1POFF);      // [256][6] (cols 0..4 used)
        ull* scr = (ull*)(sm + SCROFF);      // [4][256][5]
        ull* wt1T = (ull*)(sm + WT1OFF);     // [jp][512]
        float* bt1s = (float*)(sm + BT1OFF);
        float* b1s = (float*)(sm + B1OFF);
        float* hsm = (float*)(sm + HSOFF);
        const uint32_t mbF = smb + MBOFF;
        const uint32_t mbE = smb + MBOFF + 32;
        const int lane = t & 31, warp = t >> 5;
        const int ds = t >> 6, rbase = t & 63;

        for (int i = t; i < 1280; i += 256) {
            int d = i / 5, jp = i % 5;
            w1p[d * 6 + jp] = pk2(W1[d * 10 + 2 * jp], W1[d * 10 + 2 * jp + 1]);
        }
        for (int i = t; i < 2560; i += 256) {
            int jp = i / 512, col = i % 512;
            wt1T[jp * 512 + col] = pk2(Wt1[(2 * jp) * 512 + col], Wt1[(2 * jp + 1) * 512 + col]);
        }
        for (int i = t; i < 512; i += 256) bt1s[i] = bt1[i];
        if (t < 10) b1s[t] = b1[t];
        if (t == 0) {
            #pragma unroll
            for (int s = 0; s < 4; s++) {
                asm volatile("mbarrier.init.shared.b64 [%0], 1;" :: "r"(mbF + 8 * s) : "memory");
                asm volatile("mbarrier.init.shared.b64 [%0], 8;" :: "r"(mbE + 8 * s) : "memory");
            }
            asm volatile("fence.proxy.async.shared::cta;" ::: "memory");
        }
        BAR(1, 256);

        const int NT = (B * 32 + 255) >> 8;
        const int ntiles = (bid < NT) ? (NT - bid + G - 1) / G : 0;
        const int totc = ntiles * 8;

        auto issue = [&](int i) {
            if (i >= 4) mbar_wait(mbE + 8 * (i & 3), (uint32_t)(((i >> 2) - 1) & 1));
            int gt = bid + G * (i >> 3);
            uint32_t dst = smb + (i & 3) * BUFB;
            uint32_t mb = mbF + 8 * (i & 3);
            asm volatile("mbarrier.arrive.expect_tx.shared.b64 _, [%0], %1;"
                         :: "r"(mb), "r"(32768u) : "memory");
            int x = (i & 7) * 32, y = gt * 256;
            asm volatile("cp.async.bulk.tensor.2d.shared::cta.global.tile.mbarrier::complete_tx::bytes"
                         " [%0], [%1, {%2, %3}], [%4];"
                         :: "r"(dst), "l"(&tmap), "r"(x), "r"(y), "r"(mb) : "memory");
        };
        if (t == 0) { int pre = totc < 3 ? totc : 3; for (int i = 0; i < pre; i++) issue(i); }

        ull acc[4][5];
        #pragma unroll
        for (int q = 0; q < 4; q++)
            #pragma unroll
            for (int jp = 0; jp < 5; jp++) acc[q][jp] = 0ull;

        #pragma unroll 1
        for (int i = 0; i < totc; i++) {
            if (t == 0 && i + 3 < totc) issue(i + 3);
            mbar_wait(mbF + 8 * (i & 3), (uint32_t)((i >> 2) & 1));

            const char* bb = sm + (i & 3) * BUFB;
            const int c = i & 7;
            #pragma unroll
            for (int g = 0; g < 2; g++) {
                const int dg = c * 32 + ds * 8 + g * 4;
                ull wpk[4][5];
                #pragma unroll
                for (int dd = 0; dd < 4; dd++) {
                    const ull* wp = &w1p[(dg + dd) * 6];
                    ulonglong2 w01 = *(const ulonglong2*)wp;
                    ulonglong2 w23 = *(const ulonglong2*)(wp + 2);
                    wpk[dd][0] = w01.x; wpk[dd][1] = w01.y;
                    wpk[dd][2] = w23.x; wpk[dd][3] = w23.y;
                    wpk[dd][4] = wp[4];
                }
                #pragma unroll
                for (int q = 0; q < 4; q++) {
                    int r = rbase + 64 * q;
                    int off = r * 128 + (2 * ds + g) * 16;
                    int phys = off ^ ((r & 7) << 4);
                    float4 x = *(const float4*)(bb + phys);
                    ull p0 = pk2(x.x, x.x), p1 = pk2(x.y, x.y);
                    ull p2 = pk2(x.z, x.z), p3 = pk2(x.w, x.w);
                    #pragma unroll
                    for (int jp = 0; jp < 5; jp++) {
                        fma2(acc[q][jp], p0, wpk[0][jp]);
                        fma2(acc[q][jp], p1, wpk[1][jp]);
                        fma2(acc[q][jp], p2, wpk[2][jp]);
                        fma2(acc[q][jp], p3, wpk[3][jp]);
                    }
                }
            }

            __syncwarp();
            if (lane == 0)
                asm volatile("mbarrier.arrive.shared.b64 _, [%0];"
                             :: "r"(mbE + 8 * (i & 3)) : "memory");

            if (c == 7) {
                const int gt = bid + G * (i >> 3);
                // all threads store their 4 rows x 5 jp to scr[ds][row][jp]
                #pragma unroll
                for (int q = 0; q < 4; q++) {
                    ull* dp = &scr[((size_t)ds * 256 + rbase + 64 * q) * 5];
                    #pragma unroll
                    for (int jp = 0; jp < 5; jp++) dp[jp] = acc[q][jp];
                }
                BAR(1, 256);
                // thread t owns row t: reduce 4 slices, then warp-wide shfl-max
                // (warp w's 32 lanes = 32 neighbors of b_local = w)
                {
                    ull red[5];
                    const ull* s0 = &scr[(size_t)t * 5];
                    #pragma unroll
                    for (int jp = 0; jp < 5; jp++) red[jp] = s0[jp];
                    #pragma unroll
                    for (int s = 1; s < 4; s++) {
                        const ull* sp = &scr[((size_t)s * 256 + t) * 5];
                        #pragma unroll
                        for (int jp = 0; jp < 5; jp++) add2(red[jp], sp[jp]);
                    }
                    float h[10];
                    #pragma unroll
                    for (int jp = 0; jp < 5; jp++) {
                        float2 v = upk2(red[jp]);
                        h[2 * jp] = v.x; h[2 * jp + 1] = v.y;
                    }
                    #pragma unroll
                    for (int j = 0; j < 10; j++)
                        #pragma unroll
                        for (int o = 16; o > 0; o >>= 1)
                            h[j] = fmaxf(h[j], __shfl_xor_sync(FULLMASK, h[j], o));
                    if (lane == 0) {
                        #pragma unroll
                        for (int j = 0; j < 10; j++)
                            hsm[warp * 10 + j] = fmaxf(h[j] + b1s[j], 0.0f);
                    }
                }
                BAR(1, 256);
                // from_neighs: warp w owns cols [w*64, w*64+64); lane owns 2 cols.
                {
                    const int colA = warp * 64 + 2 * lane;
                    ull wA[5], wB[5];
                    #pragma unroll
                    for (int jp = 0; jp < 5; jp++) {
                        ulonglong2 wv = *(const ulonglong2*)&wt1T[jp * 512 + colA];
                        wA[jp] = wv.x; wB[jp] = wv.y;
                    }
                    float2 btv = *(const float2*)&bt1s[colA];
                    #pragma unroll
                    for (int b8 = 0; b8 < 8; b8++) {
                        int b = gt * 8 + b8;
                        if (b < B) {
                            const ull* hp = (const ull*)&hsm[b8 * 10];
                            ull sA = 0ull, sB = 0ull;
                            #pragma unroll
                            for (int jp = 0; jp < 5; jp++) {
                                ull hv = hp[jp];
                                fma2(sA, hv, wA[jp]);
                                fma2(sB, hv, wB[jp]);
                            }
                            float2 va = upk2(sA), vb = upk2(sB);
                            *(float2*)(out + (size_t)b * 1024 + 512 + colA) =
                                make_float2(va.x + va.y + btv.x, vb.x + vb.y + btv.y);
                        }
                    }
                }
                #pragma unroll
                for (int q = 0; q < 4; q++)
                    #pragma unroll
                    for (int jp = 0; jp < 5; jp++) acc[q][jp] = 0ull;
                BAR(1, 256);   // protect scr + hs reuse
            }
        }
    } else {
        // ================= k2: tf32 mma self @ Wt2 + bt2 =================
        float* as = (float*)(sm + K2AOFF);   // [64][20]
        float* bs = (float*)(sm + K2BOFF);   // [16][136]
        const int wt = t - 256;
        const int w = wt >> 5, lane = wt & 31;
        const int M = B;
        const int jobs = ((M + 63) >> 6) * 4;
        const int ar = lane >> 2, ak = lane & 3;

        float4 ra[2], rb[4];
        #pragma unroll 1
        for (int j = bid; j < jobs; j += G) {
            const int m0 = (j >> 2) * 64;
            const int n0 = (j & 3) * 128;

            float acc[4][4][4];
            #pragma unroll
            for (int mt = 0; mt < 4; mt++)
                #pragma unroll
                for (int nt = 0; nt < 4; nt++)
                    #pragma unroll
                    for (int e = 0; e < 4; e++) acc[mt][nt][e] = 0.f;

            #pragma unroll
            for (int i = 0; i < 2; i++) {
                int idx = wt + 128 * i, row = idx >> 2, kq = (idx & 3) << 2;
                ra[i] = make_float4(0.f, 0.f, 0.f, 0.f);
                if (m0 + row < M) ra[i] = *(const float4*)(A + (size_t)(m0 + row) * 256 + kq);
            }
            #pragma unroll
            for (int i = 0; i < 4; i++) {
                int idx = wt + 128 * i, k = idx >> 5, nq = (idx & 31) << 2;
                rb[i] = *(const float4*)(Bw + (size_t)k * 512 + n0 + nq);
            }

            #pragma unroll 1
            for (int kc = 0; kc < 16; kc++) {
                BAR(2, 128);
                #pragma unroll
                for (int i = 0; i < 2; i++) {
                    int idx = wt + 128 * i, row = idx >> 2, kq = (idx & 3) << 2;
                    *(float4*)&as[row * 20 + kq] =
                        make_float4(tf32r(ra[i].x), tf32r(ra[i].y), tf32r(ra[i].z), tf32r(ra[i].w));
                }
                #pragma unroll
                for (int i = 0; i < 4; i++) {
                    int idx = wt + 128 * i, k = idx >> 5, nq = (idx & 31) << 2;
                    *(float4*)&bs[k * 136 + nq] =
                        make_float4(tf32r(rb[i].x), tf32r(rb[i].y), tf32r(rb[i].z), tf32r(rb[i].w));
                }
                if (kc + 1 < 16) {
                    int k0 = (kc + 1) * 16;
                    #pragma unroll
                    for (int i = 0; i < 2; i++) {
                        int idx = wt + 128 * i, row = idx >> 2, kq = (idx & 3) << 2;
                        ra[i] = make_float4(0.f, 0.f, 0.f, 0.f);
                        if (m0 + row < M)
                            ra[i] = *(const float4*)(A + (size_t)(m0 + row) * 256 + k0 + kq);
                    }
                    #pragma unroll
                    for (int i = 0; i < 4; i++) {
                        int idx = wt + 128 * i, k = idx >> 5, nq = (idx & 31) << 2;
                        rb[i] = *(const float4*)(Bw + (size_t)(k0 + k) * 512 + n0 + nq);
                    }
                }
                BAR(2, 128);
                #pragma unroll
                for (int s = 0; s < 2; s++) {
                    uint32_t a[4][4];
                    #pragma unroll
                    for (int mt = 0; mt < 4; mt++) {
                        const float* ap = &as[(mt * 16 + ar) * 20 + s * 8 + ak];
                        a[mt][0] = __float_as_uint(ap[0]);
                        a[mt][1] = __float_as_uint(ap[8 * 20]);
                        a[mt][2] = __float_as_uint(ap[4]);
                        a[mt][3] = __float_as_uint(ap[8 * 20 + 4]);
                    }
                    #pragma unroll
                    for (int nt = 0; nt < 4; nt++) {
                        int nb = w * 32 + nt * 8 + ar;
                        uint32_t b0 = __float_as_uint(bs[(s * 8 + ak) * 136 + nb]);
                        uint32_t b1v = __float_as_uint(bs[(s * 8 + 4 + ak) * 136 + nb]);
                        #pragma unroll
                        for (int mt = 0; mt < 4; mt++)
                            mma8(acc[mt][nt], a[mt][0], a[mt][1], a[mt][2], a[mt][3], b0, b1v);
                    }
                }
            }

            #pragma unroll
            for (int mt = 0; mt < 4; mt++) {
                int r0 = m0 + mt * 16 + ar;
                #pragma unroll
                for (int nt = 0; nt < 4; nt++) {
                    int col = n0 + w * 32 + nt * 8 + 2 * ak;
                    float bv0 = bt2[col], bv1 = bt2[col + 1];
                    if (r0 < M)
                        *(float2*)(out + (size_t)r0 * 1024 + col) =
                            make_float2(acc[mt][nt][0] + bv0, acc[mt][nt][1] + bv1);
                    if (r0 + 8 < M)
                        *(float2*)(out + (size_t)(r0 + 8) * 1024 + col) =
                            make_float2(acc[mt][nt][2] + bv0, acc[mt][nt][3] + bv1);
                }
            }
        }
    }
}

// ---------------------------------------------------------------------------
typedef CUresult (*EncodeFn)(CUtensorMap*, CUtensorMapDataType, cuuint32_t, void*,
                             const cuuint64_t*, const cuuint64_t*, const cuuint32_t*,
                             const cuuint32_t*, CUtensorMapInterleave, CUtensorMapSwizzle,
                             CUtensorMapL2promotion, CUtensorMapFloatOOBfill);

extern "C" void kernel_launch(void* const* d_in, const int* in_sizes, int n_in,
                              void* d_out, int out_size)
{
    const float* self_vecs = (const float*)d_in[0];
    const float* neigh     = (const float*)d_in[1];
    const float* W1        = (const float*)d_in[2];
    const float* b1        = (const float*)d_in[3];
    const float* Wt1       = (const float*)d_in[4];
    const float* bt1       = (const float*)d_in[5];
    const float* Wt2       = (const float*)d_in[6];
    const float* bt2       = (const float*)d_in[7];
    float* out = (float*)d_out;

    const int B = in_sizes[0] / 256;

    EncodeFn enc = nullptr;
    cudaDriverEntryPointQueryResult qr;
    cudaGetDriverEntryPointByVersion("cuTensorMapEncodeTiled", (void**)&enc, 12000,
                                     cudaEnableDefault, &qr);
    CUtensorMap tN;
    {
        cuuint64_t gd[2] = {256ull, (cuuint64_t)B * 32ull};
        cuuint64_t gs[1] = {1024ull};
        cuuint32_t bx[2] = {32u, 256u}, es[2] = {1u, 1u};
        enc(&tN, CU_TENSOR_MAP_DATA_TYPE_FLOAT32, 2, (void*)neigh, gd, gs, bx, es,
            CU_TENSOR_MAP_INTERLEAVE_NONE, CU_TENSOR_MAP_SWIZZLE_128B,
            CU_TENSOR_MAP_L2_PROMOTION_L2_128B, CU_TENSOR_MAP_FLOAT_OOB_FILL_NONE);
    }

    cudaFuncSetAttribute(fused_all, cudaFuncAttributeMaxDynamicSharedMemorySize, SMEMT);
    fused_all<<<148, 384, SMEMT>>>(tN, W1, b1, Wt1, bt1, self_vecs, Wt2, bt2, out, B);
}

// round 16
// speedup vs baseline: 1.0361x; 1.0361x over previous
#include <cuda_runtime.h>
#include <cuda.h>
#include <cstdint>

typedef unsigned long long ull;
#define FULLMASK 0xffffffffu
#define BAR(id, n) asm volatile("bar.sync %0, %1;" :: "r"(id), "r"(n) : "memory")

__device__ __forceinline__ ull pk2(float x, float y) {
    ull r; asm("mov.b64 %0, {%1, %2};" : "=l"(r) : "f"(x), "f"(y)); return r;
}
__device__ __forceinline__ float2 upk2(ull p) {
    float2 t; asm("mov.b64 {%0, %1}, %2;" : "=f"(t.x), "=f"(t.y) : "l"(p)); return t;
}
__device__ __forceinline__ void fma2(ull& d, ull a, ull b) {
    asm("fma.rn.f32x2 %0, %1, %2, %0;" : "+l"(d) : "l"(a), "l"(b));
}
__device__ __forceinline__ void add2(ull& d, ull a) {
    asm("add.rn.f32x2 %0, %0, %1;" : "+l"(d) : "l"(a));
}
__device__ __forceinline__ float tf32r(float x) {
    uint32_t o; asm("cvt.rna.tf32.f32 %0, %1;" : "=r"(o) : "f"(x));
    return __uint_as_float(o);
}
__device__ __forceinline__ void mbar_wait(uint32_t mb, uint32_t ph) {
    uint32_t done;
    asm volatile("{\n\t.reg .pred p;\n\t"
        "mbarrier.try_wait.parity.acquire.cta.shared::cta.b64 p, [%1], %2;\n\t"
        "selp.b32 %0, 1, 0, p;\n\t}" : "=r"(done) : "r"(mb), "r"(ph) : "memory");
    while (!done) {
        asm volatile("{\n\t.reg .pred p;\n\t"
            "mbarrier.try_wait.parity.acquire.cta.shared::cta.b64 p, [%1], %2, 10000000;\n\t"
            "selp.b32 %0, 1, 0, p;\n\t}" : "=r"(done) : "r"(mb), "r"(ph) : "memory");
    }
}
__device__ __forceinline__ void mma8(float* c, uint32_t a0, uint32_t a1, uint32_t a2,
                                     uint32_t a3, uint32_t b0, uint32_t b1) {
    asm volatile("mma.sync.aligned.m16n8k8.row.col.f32.tf32.tf32.f32 "
                 "{%0,%1,%2,%3}, {%4,%5,%6,%7}, {%8,%9}, {%0,%1,%2,%3};"
                 : "+f"(c[0]), "+f"(c[1]), "+f"(c[2]), "+f"(c[3])
                 : "r"(a0), "r"(a1), "r"(a2), "r"(a3), "r"(b0), "r"(b1));
}

// ---- smem layout (bytes) ----
#define BUFB   32768                 // 256 rows x 32 floats (SW128); 4 bufs = 2 supers
#define W1POFF (4 * BUFB)            // 131072: W1 packed ull[256][6] = 12288
#define SCROFF (W1POFF + 12288)      // 143360: 3*64*4*5 ull = 30720
#define MBOFF  (SCROFF + 30720)      // 174080: full[2] @ +0, empty[2] @ +16
#define K2AOFF (MBOFF + 64)          // 174144: A [64][20] = 5120
#define K2BOFF (K2AOFF + 5120)       // 179264: B [16][136] = 8704
#define WT1OFF (K2BOFF + 8704)       // 187968: Wt1^T packed [5][512] ull = 20480
#define BT1OFF (WT1OFF + 20480)      // 208448: bt1 2048
#define B1OFF  (BT1OFF + 2048)       // 210496: b1 64
#define HSOFF  (B1OFF + 64)          // 210560: hs [8][10] = 320
#define SMEMT  (HSOFF + 320)         // 210880

__global__ void __launch_bounds__(384, 1)
fused_all(const __grid_constant__ CUtensorMap tmap,
          const float* __restrict__ W1, const float* __restrict__ b1,
          const float* __restrict__ Wt1, const float* __restrict__ bt1,
          const float* __restrict__ A, const float* __restrict__ Bw,
          const float* __restrict__ bt2, float* __restrict__ out, int B)
{
    extern __shared__ char sm[];
    const uint32_t smb = (uint32_t)__cvta_generic_to_shared(sm);
    const int t = threadIdx.x;
    const int G = gridDim.x, bid = blockIdx.x;

    if (t < 256) {
        // ================= k1 + fused from_neighs epilogue =================
        ull* w1p = (ull*)(sm + W1POFF);      // [256][6] (cols 0..4 used)
        ull* scr = (ull*)(sm + SCROFF);
        ull* wt1T = (ull*)(sm + WT1OFF);     // [jp][512]
        float* bt1s = (float*)(sm + BT1OFF);
        float* b1s = (float*)(sm + B1OFF);
        float* hsm = (float*)(sm + HSOFF);
        const uint32_t mbF = smb + MBOFF;
        const uint32_t mbE = smb + MBOFF + 16;
        const int lane = t & 31, warp = t >> 5;
        const int ds = t >> 6, rbase = t & 63;

        for (int i = t; i < 1280; i += 256) {
            int d = i / 5, jp = i % 5;
            w1p[d * 6 + jp] = pk2(W1[d * 10 + 2 * jp], W1[d * 10 + 2 * jp + 1]);
        }
        for (int i = t; i < 2560; i += 256) {
            int jp = i / 512, col = i % 512;
            wt1T[jp * 512 + col] = pk2(Wt1[(2 * jp) * 512 + col], Wt1[(2 * jp + 1) * 512 + col]);
        }
        for (int i = t; i < 512; i += 256) bt1s[i] = bt1[i];
        if (t < 10) b1s[t] = b1[t];
        if (t == 0) {
            #pragma unroll
            for (int s = 0; s < 2; s++) {
                asm volatile("mbarrier.init.shared.b64 [%0], 1;" :: "r"(mbF + 8 * s) : "memory");
                asm volatile("mbarrier.init.shared.b64 [%0], 8;" :: "r"(mbE + 8 * s) : "memory");
            }
            asm volatile("fence.proxy.async.shared::cta;" ::: "memory");
        }
        BAR(1, 256);

        const int NT = (B * 32 + 255) >> 8;
        const int ntiles = (bid < NT) ? (NT - bid + G - 1) / G : 0;
        const int totS = ntiles * 4;   // 4 supers (64KB) per 256-row tile

        auto issue = [&](int si) {
            if (si >= 2) mbar_wait(mbE + 8 * (si & 1), (uint32_t)(((si >> 1) - 1) & 1));
            int gt = bid + G * (si >> 2);
            uint32_t dst = smb + (si & 1) * (2 * BUFB);
            uint32_t mb = mbF + 8 * (si & 1);
            asm volatile("mbarrier.arrive.expect_tx.shared.b64 _, [%0], %1;"
                         :: "r"(mb), "r"(65536u) : "memory");
            int x = (si & 3) * 64, y = gt * 256;
            asm volatile("cp.async.bulk.tensor.2d.shared::cta.global.tile.mbarrier::complete_tx::bytes"
                         " [%0], [%1, {%2, %3}], [%4];"
                         :: "r"(dst), "l"(&tmap), "r"(x), "r"(y), "r"(mb) : "memory");
            asm volatile("cp.async.bulk.tensor.2d.shared::cta.global.tile.mbarrier::complete_tx::bytes"
                         " [%0], [%1, {%2, %3}], [%4];"
                         :: "r"(dst + BUFB), "l"(&tmap), "r"(x + 32), "r"(y), "r"(mb) : "memory");
        };
        if (t == 0) { int pre = totS < 2 ? totS : 2; for (int s = 0; s < pre; s++) issue(s); }

        ull acc[4][5];
        #pragma unroll
        for (int q = 0; q < 4; q++)
            #pragma unroll
            for (int jp = 0; jp < 5; jp++) acc[q][jp] = 0ull;

        #pragma unroll 1
        for (int i = 0; i < totS; i++) {
            mbar_wait(mbF + 8 * (i & 1), (uint32_t)((i >> 1) & 1));

            #pragma unroll
            for (int cc = 0; cc < 2; cc++) {
                const char* bb = sm + ((i & 1) * 2 + cc) * BUFB;
                const int c = (i & 3) * 2 + cc;
                #pragma unroll
                for (int g = 0; g < 2; g++) {
                    const int dg = c * 32 + ds * 8 + g * 4;
                    ull wpk[4][5];
                    #pragma unroll
                    for (int dd = 0; dd < 4; dd++) {
                        const ull* wp = &w1p[(dg + dd) * 6];
                        ulonglong2 w01 = *(const ulonglong2*)wp;
                        ulonglong2 w23 = *(const ulonglong2*)(wp + 2);
                        wpk[dd][0] = w01.x; wpk[dd][1] = w01.y;
                        wpk[dd][2] = w23.x; wpk[dd][3] = w23.y;
                        wpk[dd][4] = wp[4];
                    }
                    #pragma unroll
                    for (int q = 0; q < 4; q++) {
                        int r = rbase + 64 * q;
                        int off = r * 128 + (2 * ds + g) * 16;
                        int phys = off ^ ((r & 7) << 4);
                        float4 x = *(const float4*)(bb + phys);
                        ull p0 = pk2(x.x, x.x), p1 = pk2(x.y, x.y);
                        ull p2 = pk2(x.z, x.z), p3 = pk2(x.w, x.w);
                        #pragma unroll
                        for (int jp = 0; jp < 5; jp++) {
                            fma2(acc[q][jp], p0, wpk[0][jp]);
                            fma2(acc[q][jp], p1, wpk[1][jp]);
                            fma2(acc[q][jp], p2, wpk[2][jp]);
                            fma2(acc[q][jp], p3, wpk[3][jp]);
                        }
                    }
                }
            }

            __syncwarp();
            if (lane == 0)
                asm volatile("mbarrier.arrive.shared.b64 _, [%0];"
                             :: "r"(mbE + 8 * (i & 1)) : "memory");
            if (t == 0 && i + 2 < totS) issue(i + 2);

            if ((i & 3) == 3) {
                const int gt = bid + G * (i >> 2);
                if (ds) {
                    ull* dp = scr + (((ds - 1) * 64 + rbase) * 4) * 5;
                    #pragma unroll
                    for (int q = 0; q < 4; q++)
                        #pragma unroll
                        for (int jp = 0; jp < 5; jp++) dp[q * 5 + jp] = acc[q][jp];
                }
                BAR(1, 256);
                if (ds == 0) {
                    // reduce d-slices, pool, relu(+b1), stage to hs
                    #pragma unroll
                    for (int s = 0; s < 3; s++) {
                        const ull* sp = scr + ((s * 64 + rbase) * 4) * 5;
                        #pragma unroll
                        for (int q = 0; q < 4; q++)
                            #pragma unroll
                            for (int jp = 0; jp < 5; jp++) add2(acc[q][jp], sp[q * 5 + jp]);
                    }
                    #pragma unroll
                    for (int q = 0; q < 4; q++) {
                        float h[10];
                        #pragma unroll
                        for (int jp = 0; jp < 5; jp++) {
                            float2 v = upk2(acc[q][jp]);
                            h[2 * jp] = v.x; h[2 * jp + 1] = v.y;
                        }
                        #pragma unroll
                        for (int j = 0; j < 10; j++)
                            #pragma unroll
                            for (int o = 16; o > 0; o >>= 1)
                                h[j] = fmaxf(h[j], __shfl_xor_sync(FULLMASK, h[j], o));
                        if (lane == 0) {
                            #pragma unroll
                            for (int j = 0; j < 10; j++)
                                hsm[(2 * q + warp) * 10 + j] = fmaxf(h[j] + b1s[j], 0.0f);
                        }
                    }
                }
                BAR(1, 256);
                // from_neighs: warp w owns cols [w*64, w*64+64); lane owns 2 cols.
                {
                    const int colA = warp * 64 + 2 * lane;
                    ull wA[5], wB[5];
                    #pragma unroll
                    for (int jp = 0; jp < 5; jp++) {
                        ulonglong2 wv = *(const ulonglong2*)&wt1T[jp * 512 + colA];
                        wA[jp] = wv.x; wB[jp] = wv.y;
                    }
                    float2 btv = *(const float2*)&bt1s[colA];
                    #pragma unroll
                    for (int b8 = 0; b8 < 8; b8++) {
                        int b = gt * 8 + b8;
                        if (b < B) {
                            const ull* hp = (const ull*)&hsm[b8 * 10];
                            ull sA = 0ull, sB = 0ull;
                            #pragma unroll
                            for (int jp = 0; jp < 5; jp++) {
                                ull hv = hp[jp];
                                fma2(sA, hv, wA[jp]);
                                fma2(sB, hv, wB[jp]);
                            }
                            float2 va = upk2(sA), vb = upk2(sB);
                            *(float2*)(out + (size_t)b * 1024 + 512 + colA) =
                                make_float2(va.x + va.y + btv.x, vb.x + vb.y + btv.y);
                        }
                    }
                }
                #pragma unroll
                for (int q = 0; q < 4; q++)
                    #pragma unroll
                    for (int jp = 0; jp < 5; jp++) acc[q][jp] = 0ull;
                BAR(1, 256);   // protect scr + hs reuse
            }
        }
    } else {
        // ================= k2: tf32 mma self @ Wt2 + bt2 =================
        float* as = (float*)(sm + K2AOFF);   // [64][20]
        float* bs = (float*)(sm + K2BOFF);   // [16][136]
        const int wt = t - 256;
        const int w = wt >> 5, lane = wt & 31;
        const int M = B;
        const int jobs = ((M + 63) >> 6) * 4;
        const int ar = lane >> 2, ak = lane & 3;

        float4 ra[2], rb[4];
        #pragma unroll 1
        for (int j = bid; j < jobs; j += G) {
            const int m0 = (j >> 2) * 64;
            const int n0 = (j & 3) * 128;

            float acc[4][4][4];
            #pragma unroll
            for (int mt = 0; mt < 4; mt++)
                #pragma unroll
                for (int nt = 0; nt < 4; nt++)
                    #pragma unroll
                    for (int e = 0; e < 4; e++) acc[mt][nt][e] = 0.f;

            #pragma unroll
            for (int i = 0; i < 2; i++) {
                int idx = wt + 128 * i, row = idx >> 2, kq = (idx & 3) << 2;
                ra[i] = make_float4(0.f, 0.f, 0.f, 0.f);
                if (m0 + row < M) ra[i] = *(const float4*)(A + (size_t)(m0 + row) * 256 + kq);
            }
            #pragma unroll
            for (int i = 0; i < 4; i++) {
                int idx = wt + 128 * i, k = idx >> 5, nq = (idx & 31) << 2;
                rb[i] = *(const float4*)(Bw + (size_t)k * 512 + n0 + nq);
            }

            #pragma unroll 1
            for (int kc = 0; kc < 16; kc++) {
                BAR(2, 128);
                #pragma unroll
                for (int i = 0; i < 2; i++) {
                    int idx = wt + 128 * i, row = idx >> 2, kq = (idx & 3) << 2;
                    *(float4*)&as[row * 20 + kq] =
                        make_float4(tf32r(ra[i].x), tf32r(ra[i].y), tf32r(ra[i].z), tf32r(ra[i].w));
                }
                #pragma unroll
                for (int i = 0; i < 4; i++) {
                    int idx = wt + 128 * i, k = idx >> 5, nq = (idx & 31) << 2;
                    *(float4*)&bs[k * 136 + nq] =
                        make_float4(tf32r(rb[i].x), tf32r(rb[i].y), tf32r(rb[i].z), tf32r(rb[i].w));
                }
                if (kc + 1 < 16) {
                    int k0 = (kc + 1) * 16;
                    #pragma unroll
                    for (int i = 0; i < 2; i++) {
                        int idx = wt + 128 * i, row = idx >> 2, kq = (idx & 3) << 2;
                        ra[i] = make_float4(0.f, 0.f, 0.f, 0.f);
                        if (m0 + row < M)
                            ra[i] = *(const float4*)(A + (size_t)(m0 + row) * 256 + k0 + kq);
                    }
                    #pragma unroll
                    for (int i = 0; i < 4; i++) {
                        int idx = wt + 128 * i, k = idx >> 5, nq = (idx & 31) << 2;
                        rb[i] = *(const float4*)(Bw + (size_t)(k0 + k) * 512 + n0 + nq);
                    }
                }
                BAR(2, 128);
                #pragma unroll
                for (int s = 0; s < 2; s++) {
                    uint32_t a[4][4];
                    #pragma unroll
                    for (int mt = 0; mt < 4; mt++) {
                        const float* ap = &as[(mt * 16 + ar) * 20 + s * 8 + ak];
                        a[mt][0] = __float_as_uint(ap[0]);
                        a[mt][1] = __float_as_uint(ap[8 * 20]);
                        a[mt][2] = __float_as_uint(ap[4]);
                        a[mt][3] = __float_as_uint(ap[8 * 20 + 4]);
                    }
                    #pragma unroll
                    for (int nt = 0; nt < 4; nt++) {
                        int nb = w * 32 + nt * 8 + ar;
                        uint32_t b0 = __float_as_uint(bs[(s * 8 + ak) * 136 + nb]);
                        uint32_t b1v = __float_as_uint(bs[(s * 8 + 4 + ak) * 136 + nb]);
                        #pragma unroll
                        for (int mt = 0; mt < 4; mt++)
                            mma8(acc[mt][nt], a[mt][0], a[mt][1], a[mt][2], a[mt][3], b0, b1v);
                    }
                }
            }

            #pragma unroll
            for (int mt = 0; mt < 4; mt++) {
                int r0 = m0 + mt * 16 + ar;
                #pragma unroll
                for (int nt = 0; nt < 4; nt++) {
                    int col = n0 + w * 32 + nt * 8 + 2 * ak;
                    float bv0 = bt2[col], bv1 = bt2[col + 1];
                    if (r0 < M)
                        *(float2*)(out + (size_t)r0 * 1024 + col) =
                            make_float2(acc[mt][nt][0] + bv0, acc[mt][nt][1] + bv1);
                    if (r0 + 8 < M)
                        *(float2*)(out + (size_t)(r0 + 8) * 1024 + col) =
                            make_float2(acc[mt][nt][2] + bv0, acc[mt][nt][3] + bv1);
                }
            }
        }
    }
}

// ---------------------------------------------------------------------------
typedef CUresult (*EncodeFn)(CUtensorMap*, CUtensorMapDataType, cuuint32_t, void*,
                             const cuuint64_t*, const cuuint64_t*, const cuuint32_t*,
                             const cuuint32_t*, CUtensorMapInterleave, CUtensorMapSwizzle,
                             CUtensorMapL2promotion, CUtensorMapFloatOOBfill);

extern "C" void kernel_launch(void* const* d_in, const int* in_sizes, int n_in,
                              void* d_out, int out_size)
{
    const float* self_vecs = (const float*)d_in[0];
    const float* neigh     = (const float*)d_in[1];
    const float* W1        = (const float*)d_in[2];
    const float* b1        = (const float*)d_in[3];
    const float* Wt1       = (const float*)d_in[4];
    const float* bt1       = (const float*)d_in[5];
    const float* Wt2       = (const float*)d_in[6];
    const float* bt2       = (const float*)d_in[7];
    float* out = (float*)d_out;

    const int B = in_sizes[0] / 256;

    EncodeFn enc = nullptr;
    cudaDriverEntryPointQueryResult qr;
    cudaGetDriverEntryPointByVersion("cuTensorMapEncodeTiled", (void**)&enc, 12000,
                                     cudaEnableDefault, &qr);
    CUtensorMap tN;
    {
        cuuint64_t gd[2] = {256ull, (cuuint64_t)B * 32ull};
        cuuint64_t gs[1] = {1024ull};
        cuuint32_t bx[2] = {32u, 256u}, es[2] = {1u, 1u};
        enc(&tN, CU_TENSOR_MAP_DATA_TYPE_FLOAT32, 2, (void*)neigh, gd, gs, bx, es,
            CU_TENSOR_MAP_INTERLEAVE_NONE, CU_TENSOR_MAP_SWIZZLE_128B,
            CU_TENSOR_MAP_L2_PROMOTION_L2_128B, CU_TENSOR_MAP_FLOAT_OOB_FILL_NONE);
    }

    cudaFuncSetAttribute(fused_all, cudaFuncAttributeMaxDynamicSharedMemorySize, SMEMT);
    fused_all<<<148, 384, SMEMT>>>(tN, W1, b1, Wt1, bt1, self_vecs, Wt2, bt2, out, B);
}